// round 12
// baseline (speedup 1.0000x reference)
#include <cuda_runtime.h>
#include <cstdint>

// ChamferDistance on GB300 — Round 12: exact NN, warp-autonomous pruned scan.
// Stage 1: counting-sort both sets by z into 256 buckets; store SoA
//          (g_sx/g_sy/g_sz/g_sq) + original index.
// Stage 2: each WARP owns 64 contiguous sorted queries (32 lanes x QP=2),
//          scans refs via warp-uniform broadcast LDG.64 from the SoA arrays
//          (L1-resident), expands its own z-window with per-query union
//          bounds (SHFL reductions only). No smem, no __syncthreads.
// Exact: refs outside [min_q(zq-sqrt(dq)), max_q(zq+sqrt(dq))] cannot improve
// any query's min. Each output written exactly once.

#define NB    256
#define ST    256          // sort threads
#define QT    128          // NN threads (4 warps)
#define QP    2            // queries per thread -> 64 per warp
#define WQ    (32 * QP)
#define BSTEP 4            // buckets per expansion step
#define PAD   4            // initial window padding (buckets)
#define MAXP  8192
#define MAXB  8

__device__ float g_sx [2][MAXB * MAXP];
__device__ float g_sy [2][MAXB * MAXP];
__device__ float g_sz [2][MAXB * MAXP];
__device__ float g_sq [2][MAXB * MAXP];
__device__ int   g_idx[2][MAXB * MAXP];
__device__ int   g_off[2][MAXB][NB + 1];
__device__ float g_zmin[2][MAXB];
__device__ float g_w   [2][MAXB];
__device__ float g_invw[2][MAXB];

// ---------------- Stage 1: z counting sort (SoA output) ----------------
__global__ __launch_bounds__(ST)
void cd_bucket_kernel(const float* __restrict__ xyz1,
                      const float* __restrict__ xyz2,
                      int Npts)
{
    const int set = blockIdx.y;
    const int b   = blockIdx.x;
    const float* __restrict__ src =
        ((set == 0) ? xyz1 : xyz2) + (size_t)b * Npts * 3;
    const int tid = threadIdx.x;

    __shared__ float s_red[ST];
    __shared__ int   s_hist[NB];
    __shared__ int   s_off[NB + 1];
    __shared__ int   s_cur[NB];
    __shared__ float s_zmin, s_invw;

    float zmn = 3.402823466e+38f, zmx = -3.402823466e+38f;
    for (int j = tid; j < Npts; j += ST) {
        float z = src[j * 3 + 2];
        zmn = fminf(zmn, z);
        zmx = fmaxf(zmx, z);
    }
    s_red[tid] = zmn; __syncthreads();
    for (int s = ST / 2; s > 0; s >>= 1) {
        if (tid < s) s_red[tid] = fminf(s_red[tid], s_red[tid + s]);
        __syncthreads();
    }
    float zlo = s_red[0]; __syncthreads();
    s_red[tid] = zmx; __syncthreads();
    for (int s = ST / 2; s > 0; s >>= 1) {
        if (tid < s) s_red[tid] = fmaxf(s_red[tid], s_red[tid + s]);
        __syncthreads();
    }
    if (tid == 0) {
        float zhi = s_red[0];
        float w = (zhi - zlo) / NB;
        if (!(w > 0.f)) w = 1e-30f;
        s_zmin = zlo;
        s_invw = 1.0f / w;
        g_zmin[set][b] = zlo;
        g_w[set][b]    = w;
        g_invw[set][b] = 1.0f / w;
    }
    if (tid < NB) s_hist[tid] = 0;
    __syncthreads();

    for (int j = tid; j < Npts; j += ST) {
        float z = src[j * 3 + 2];
        int bb = min(NB - 1, max(0, (int)((z - s_zmin) * s_invw)));
        atomicAdd(&s_hist[bb], 1);
    }
    __syncthreads();
    if (tid == 0) {
        int acc = 0;
        for (int i = 0; i < NB; i++) { s_off[i] = acc; acc += s_hist[i]; }
        s_off[NB] = acc;
    }
    __syncthreads();
    if (tid < NB) s_cur[tid] = s_off[tid];
    g_off[set][b][tid] = s_off[tid];
    if (tid == 0) g_off[set][b][NB] = s_off[NB];
    __syncthreads();

    const size_t bo = (size_t)b * Npts;
    for (int j = tid; j < Npts; j += ST) {
        float x = src[j * 3 + 0];
        float y = src[j * 3 + 1];
        float z = src[j * 3 + 2];
        int bb = min(NB - 1, max(0, (int)((z - s_zmin) * s_invw)));
        int pos = atomicAdd(&s_cur[bb], 1);
        g_sx[set][bo + pos] = x;
        g_sy[set][bo + pos] = y;
        g_sz[set][bo + pos] = z;
        g_sq[set][bo + pos] = fmaf(x, x, fmaf(y, y, z * z));
        g_idx[set][bo + pos] = j;
    }
}

// ---------------- helpers ----------------
__device__ __forceinline__ uint64_t cd_dup2(float v) {
    uint64_t r;
    asm("mov.b64 %0, {%1, %1};" : "=l"(r) : "r"(__float_as_uint(v)));
    return r;
}

__device__ __forceinline__ void cd_dot2(uint64_t qx, uint64_t qy, uint64_t qz,
                                        uint64_t px, uint64_t py, uint64_t pz,
                                        uint64_t s,
                                        float& dlo, float& dhi) {
    uint32_t lo, hi;
    asm("{\n\t"
        ".reg .b64 t;\n\t"
        "fma.rn.f32x2 t, %2, %3, %4;\n\t"
        "fma.rn.f32x2 t, %5, %6, t;\n\t"
        "fma.rn.f32x2 t, %7, %8, t;\n\t"
        "mov.b64 {%0, %1}, t;\n\t"
        "}"
        : "=r"(lo), "=r"(hi)
        : "l"(qz), "l"(pz), "l"(s),
          "l"(qy), "l"(py),
          "l"(qx), "l"(px));
    dlo = __uint_as_float(lo);
    dhi = __uint_as_float(hi);
}

__device__ __forceinline__ float wmax(float v) {
    #pragma unroll
    for (int o = 16; o; o >>= 1) v = fmaxf(v, __shfl_xor_sync(0xFFFFFFFFu, v, o));
    return v;
}
__device__ __forceinline__ float wmin(float v) {
    #pragma unroll
    for (int o = 16; o; o >>= 1) v = fminf(v, __shfl_xor_sync(0xFFFFFFFFu, v, o));
    return v;
}

// ---------------- Stage 2: warp-autonomous pruned NN ----------------
__global__ __launch_bounds__(QT, 6)
void cd_nn_kernel(float* __restrict__ out, int Npts, int B)
{
    const int dir  = blockIdx.z;
    const int b    = blockIdx.y;
    const int qset = dir, rset = 1 - dir;
    const int tid  = threadIdx.x;
    const int lane = tid & 31;
    const int warp = tid >> 5;

    const size_t qo = (size_t)b * Npts;
    const float* __restrict__ QX = &g_sx[qset][qo];
    const float* __restrict__ QY = &g_sy[qset][qo];
    const float* __restrict__ QZ = &g_sz[qset][qo];
    const float* __restrict__ QS = &g_sq[qset][qo];
    const int*   __restrict__ QI = &g_idx[qset][qo];

    const uint64_t* __restrict__ RX2 = (const uint64_t*)&g_sx[rset][qo];
    const uint64_t* __restrict__ RY2 = (const uint64_t*)&g_sy[rset][qo];
    const uint64_t* __restrict__ RZ2 = (const uint64_t*)&g_sz[rset][qo];
    const uint64_t* __restrict__ RS2 = (const uint64_t*)&g_sq[rset][qo];
    const int* __restrict__ off = g_off[rset][b];
    const float zminR = g_zmin[rset][b];
    const float wR    = g_w[rset][b];
    const float invwR = g_invw[rset][b];

    const int qbase = (blockIdx.x * (QT / 32) + warp) * WQ;

    // Per-thread queries (sorted, contiguous per warp)
    uint64_t qxd[QP], qyd[QP], qzd[QP];
    float qsq[QP], zq[QP], me[QP];
    int qidx[QP];
    #pragma unroll
    for (int p = 0; p < QP; p++) {
        int ii = qbase + p * 32 + lane;
        qidx[p] = ii;
        float x = QX[ii], y = QY[ii], z = QZ[ii];
        qxd[p] = cd_dup2(-2.0f * x);
        qyd[p] = cd_dup2(-2.0f * y);
        qzd[p] = cd_dup2(-2.0f * z);
        qsq[p] = QS[ii];
        zq[p]  = z;
        me[p]  = 3.402823466e+38f;
    }

    float zqmin = wmin(fminf(zq[0], zq[1]));
    float zqmax = wmax(fmaxf(zq[0], zq[1]));

    // Warp-uniform scan of ref index range [j0, j1) (rounded to u64 pairs).
    auto scan = [&](int j0, int j1) {
        j0 &= ~1;
        j1 = (j1 + 1) & ~1;           // Npts even -> stays in range
        int e = j1 >> 1;
        #pragma unroll 2
        for (int j2 = j0 >> 1; j2 < e; ++j2) {
            uint64_t px = RX2[j2];    // warp-uniform broadcast loads
            uint64_t py = RY2[j2];
            uint64_t pz = RZ2[j2];
            uint64_t ps = RS2[j2];
            #pragma unroll
            for (int p = 0; p < QP; p++) {
                float dlo, dhi;
                cd_dot2(qxd[p], qyd[p], qzd[p], px, py, pz, ps, dlo, dhi);
                me[p] = fminf(me[p], fminf(dlo, dhi));
            }
        }
    };

    // Initial window: query z-span padded by PAD buckets.
    int bq_lo = min(NB - 1, max(0, (int)((zqmin - zminR) * invwR)));
    int bq_hi = min(NB - 1, max(0, (int)((zqmax - zminR) * invwR)));
    int blo = max(bq_lo - PAD, 0);
    int bhi = min(bq_hi + 1 + PAD, NB);
    scan(off[blo], off[bhi]);

    // Expansion with per-query union bounds (warp-uniform, divergence-free).
    for (;;) {
        float r0 = sqrtf(fmaxf(me[0] + qsq[0], 0.0f));
        float r1 = sqrtf(fmaxf(me[1] + qsq[1], 0.0f));
        float hi_need = wmax(fmaxf(zq[0] + r0, zq[1] + r1));
        float lo_need = wmin(fminf(zq[0] - r0, zq[1] - r1));

        bool okLo = (blo > 0)  && (zminR + (float)blo * wR > lo_need);
        bool okHi = (bhi < NB) && (zminR + (float)bhi * wR < hi_need);
        if (!okLo && !okHi) break;
        if (okLo) {
            int nlo = max(blo - BSTEP, 0);
            scan(off[nlo], off[blo]);
            blo = nlo;
        }
        if (okHi) {
            int nhi = min(bhi + BSTEP, NB);
            scan(off[bhi], off[nhi]);
            bhi = nhi;
        }
    }

    float* __restrict__ o = out + ((dir == 0) ? 0 : (size_t)B * Npts)
                          + (size_t)b * Npts;
    #pragma unroll
    for (int p = 0; p < QP; p++) {
        float d = fmaxf(me[p] + qsq[p], 0.0f);
        o[QI[qidx[p]]] = d;
    }
}

extern "C" void kernel_launch(void* const* d_in, const int* in_sizes, int n_in,
                              void* d_out, int out_size)
{
    const float* xyz1 = (const float*)d_in[0];
    const float* xyz2 = (const float*)d_in[1];
    float* out = (float*)d_out;

    const int B = 8;
    const int N = (in_sizes[0] / 3) / B;   // 8192 (== M)

    {
        dim3 grid(B, 2);
        cd_bucket_kernel<<<grid, ST>>>(xyz1, xyz2, N);
    }
    {
        int qblocks = N / (QT * QP);              // 32 CTAs per (b,dir)
        dim3 grid(qblocks, B, 2);                 // 32 x 8 x 2 = 512 CTAs
        cd_nn_kernel<<<grid, QT>>>(out, N, B);
    }
}

// round 13
// speedup vs baseline: 1.7676x; 1.7676x over previous
#include <cuda_runtime.h>
#include <cstdint>

// ChamferDistance on GB300 — Round 13: exact NN, warp-autonomous pruned scan
// with warp-private smem staging + register double-buffering.
// Stage 1: counting-sort both sets by z into 256 buckets (SoA + orig idx).
// Stage 2: each warp owns 64 contiguous sorted queries (32 lanes x QP=2).
//   Per 64-ref tile: 2 coalesced LDG.128 per lane-group prefetched into regs,
//   STS to warp-private smem, broadcast-LDS f32x2-FFMA inner loop (R5 math).
//   Window expansion by per-query union bound (SHFL only, no block syncs).

#define NB    256
#define ST    256
#define QT    128          // 4 warps per CTA
#define QP    2            // queries per thread -> 64 per warp
#define WQ    (32 * QP)
#define TW    64           // refs per warp tile (1KB smem)
#define BSTEP 2
#define PAD   2
#define MAXP  8192
#define MAXB  8

__device__ float g_sx [2][MAXB * MAXP];
__device__ float g_sy [2][MAXB * MAXP];
__device__ float g_sz [2][MAXB * MAXP];
__device__ float g_sq [2][MAXB * MAXP];
__device__ int   g_idx[2][MAXB * MAXP];
__device__ int   g_off[2][MAXB][NB + 1];
__device__ float g_zmin[2][MAXB];
__device__ float g_w   [2][MAXB];
__device__ float g_invw[2][MAXB];

// ---------------- Stage 1: z counting sort (SoA output) ----------------
__global__ __launch_bounds__(ST)
void cd_bucket_kernel(const float* __restrict__ xyz1,
                      const float* __restrict__ xyz2,
                      int Npts)
{
    const int set = blockIdx.y;
    const int b   = blockIdx.x;
    const float* __restrict__ src =
        ((set == 0) ? xyz1 : xyz2) + (size_t)b * Npts * 3;
    const int tid = threadIdx.x;

    __shared__ float s_red[ST];
    __shared__ int   s_hist[NB];
    __shared__ int   s_off[NB + 1];
    __shared__ int   s_cur[NB];
    __shared__ float s_zmin, s_invw;

    float zmn = 3.402823466e+38f, zmx = -3.402823466e+38f;
    for (int j = tid; j < Npts; j += ST) {
        float z = src[j * 3 + 2];
        zmn = fminf(zmn, z);
        zmx = fmaxf(zmx, z);
    }
    s_red[tid] = zmn; __syncthreads();
    for (int s = ST / 2; s > 0; s >>= 1) {
        if (tid < s) s_red[tid] = fminf(s_red[tid], s_red[tid + s]);
        __syncthreads();
    }
    float zlo = s_red[0]; __syncthreads();
    s_red[tid] = zmx; __syncthreads();
    for (int s = ST / 2; s > 0; s >>= 1) {
        if (tid < s) s_red[tid] = fmaxf(s_red[tid], s_red[tid + s]);
        __syncthreads();
    }
    if (tid == 0) {
        float zhi = s_red[0];
        float w = (zhi - zlo) / NB;
        if (!(w > 0.f)) w = 1e-30f;
        s_zmin = zlo;
        s_invw = 1.0f / w;
        g_zmin[set][b] = zlo;
        g_w[set][b]    = w;
        g_invw[set][b] = 1.0f / w;
    }
    if (tid < NB) s_hist[tid] = 0;
    __syncthreads();

    for (int j = tid; j < Npts; j += ST) {
        float z = src[j * 3 + 2];
        int bb = min(NB - 1, max(0, (int)((z - s_zmin) * s_invw)));
        atomicAdd(&s_hist[bb], 1);
    }
    __syncthreads();
    if (tid == 0) {
        int acc = 0;
        for (int i = 0; i < NB; i++) { s_off[i] = acc; acc += s_hist[i]; }
        s_off[NB] = acc;
    }
    __syncthreads();
    if (tid < NB) s_cur[tid] = s_off[tid];
    g_off[set][b][tid] = s_off[tid];
    if (tid == 0) g_off[set][b][NB] = s_off[NB];
    __syncthreads();

    const size_t bo = (size_t)b * Npts;
    for (int j = tid; j < Npts; j += ST) {
        float x = src[j * 3 + 0];
        float y = src[j * 3 + 1];
        float z = src[j * 3 + 2];
        int bb = min(NB - 1, max(0, (int)((z - s_zmin) * s_invw)));
        int pos = atomicAdd(&s_cur[bb], 1);
        g_sx[set][bo + pos] = x;
        g_sy[set][bo + pos] = y;
        g_sz[set][bo + pos] = z;
        g_sq[set][bo + pos] = fmaf(x, x, fmaf(y, y, z * z));
        g_idx[set][bo + pos] = j;
    }
}

// ---------------- helpers ----------------
__device__ __forceinline__ uint64_t cd_dup2(float v) {
    uint64_t r;
    asm("mov.b64 %0, {%1, %1};" : "=l"(r) : "r"(__float_as_uint(v)));
    return r;
}

__device__ __forceinline__ void cd_dot2(uint64_t qx, uint64_t qy, uint64_t qz,
                                        uint64_t px, uint64_t py, uint64_t pz,
                                        uint64_t s,
                                        float& dlo, float& dhi) {
    uint32_t lo, hi;
    asm("{\n\t"
        ".reg .b64 t;\n\t"
        "fma.rn.f32x2 t, %2, %3, %4;\n\t"
        "fma.rn.f32x2 t, %5, %6, t;\n\t"
        "fma.rn.f32x2 t, %7, %8, t;\n\t"
        "mov.b64 {%0, %1}, t;\n\t"
        "}"
        : "=r"(lo), "=r"(hi)
        : "l"(qz), "l"(pz), "l"(s),
          "l"(qy), "l"(py),
          "l"(qx), "l"(px));
    dlo = __uint_as_float(lo);
    dhi = __uint_as_float(hi);
}

__device__ __forceinline__ float wmax(float v) {
    #pragma unroll
    for (int o = 16; o; o >>= 1) v = fmaxf(v, __shfl_xor_sync(0xFFFFFFFFu, v, o));
    return v;
}
__device__ __forceinline__ float wmin(float v) {
    #pragma unroll
    for (int o = 16; o; o >>= 1) v = fminf(v, __shfl_xor_sync(0xFFFFFFFFu, v, o));
    return v;
}

// ---------------- Stage 2: warp-autonomous pruned NN ----------------
__global__ __launch_bounds__(QT, 6)
void cd_nn_kernel(float* __restrict__ out, int Npts, int B)
{
    const int dir  = blockIdx.z;
    const int b    = blockIdx.y;
    const int qset = dir, rset = 1 - dir;
    const int tid  = threadIdx.x;
    const int lane = tid & 31;
    const int warp = tid >> 5;

    const size_t qo = (size_t)b * Npts;
    const float* __restrict__ QX = &g_sx[qset][qo];
    const float* __restrict__ QY = &g_sy[qset][qo];
    const float* __restrict__ QZ = &g_sz[qset][qo];
    const float* __restrict__ QS = &g_sq[qset][qo];
    const int*   __restrict__ QI = &g_idx[qset][qo];

    const float4* __restrict__ RX4 = (const float4*)&g_sx[rset][qo];
    const float4* __restrict__ RY4 = (const float4*)&g_sy[rset][qo];
    const float4* __restrict__ RZ4 = (const float4*)&g_sz[rset][qo];
    const float4* __restrict__ RQ4 = (const float4*)&g_sq[rset][qo];
    const int* __restrict__ off = g_off[rset][b];
    const float zminR = g_zmin[rset][b];
    const float wR    = g_w[rset][b];
    const float invwR = g_invw[rset][b];

    // Warp-private staging buffers: [warp][arr*TW + i], arrs = x,y,z,sq
    __shared__ __align__(16) float sw[QT / 32][4 * TW];

    const int qbase = (blockIdx.x * (QT / 32) + warp) * WQ;

    uint64_t qxd[QP], qyd[QP], qzd[QP];
    float qsq[QP], zq[QP], me[QP];
    int qidx[QP];
    #pragma unroll
    for (int p = 0; p < QP; p++) {
        int ii = qbase + p * 32 + lane;
        qidx[p] = ii;
        float x = QX[ii], y = QY[ii], z = QZ[ii];
        qxd[p] = cd_dup2(-2.0f * x);
        qyd[p] = cd_dup2(-2.0f * y);
        qzd[p] = cd_dup2(-2.0f * z);
        qsq[p] = QS[ii];
        zq[p]  = z;
        me[p]  = 3.402823466e+38f;
    }

    float zqmin = wmin(fminf(zq[0], zq[1]));
    float zqmax = wmax(fmaxf(zq[0], zq[1]));

    // Staging lane roles: lanes 0-15 load x+z chunks, lanes 16-31 load y+sq.
    const int k4 = (lane & 15) << 2;   // float offset within tile
    const int hi = lane >> 4;          // 0: x/z, 1: y/sq
    const float4* __restrict__ SA = hi ? RY4 : RX4;
    const float4* __restrict__ SB = hi ? RQ4 : RZ4;
    const float padB = hi ? 3.402823466e+38f : 0.0f;  // sq pad=inf, z pad=0

    float4 ra, rb;   // prefetch registers

    auto ldtile = [&](int jt, int j1a) {
        int idx = jt + k4;
        if (idx < j1a) {
            ra = SA[idx >> 2];
            rb = SB[idx >> 2];
        } else {
            ra = make_float4(0.f, 0.f, 0.f, 0.f);
            rb = make_float4(padB, padB, padB, padB);
        }
    };

    // Scan refs in [j0, j1): tiles of TW, smem-staged, register-prefetched.
    auto scan = [&](int j0, int j1) {
        j0 &= ~3;
        j1 = min((j1 + 3) & ~3, Npts);
        if (j0 >= j1) return;
        ldtile(j0, j1);
        for (int jt = j0; jt < j1; jt += TW) {
            __syncwarp();                       // prior tile's readers done
            *(float4*)&sw[warp][hi * TW + k4]       = ra;
            *(float4*)&sw[warp][(2 + hi) * TW + k4] = rb;
            __syncwarp();
            int nx = jt + TW;
            if (nx < j1) ldtile(nx, j1);        // prefetch next tile
            const uint64_t* __restrict__ px2 = (const uint64_t*)&sw[warp][0];
            const uint64_t* __restrict__ py2 = (const uint64_t*)&sw[warp][TW];
            const uint64_t* __restrict__ pz2 = (const uint64_t*)&sw[warp][2 * TW];
            const uint64_t* __restrict__ ps2 = (const uint64_t*)&sw[warp][3 * TW];
            #pragma unroll 4
            for (int jj = 0; jj < TW / 2; jj++) {
                uint64_t px = px2[jj], py = py2[jj];
                uint64_t pz = pz2[jj], ps = ps2[jj];
                #pragma unroll
                for (int p = 0; p < QP; p++) {
                    float dlo, dhi2;
                    cd_dot2(qxd[p], qyd[p], qzd[p], px, py, pz, ps, dlo, dhi2);
                    me[p] = fminf(me[p], fminf(dlo, dhi2));
                }
            }
        }
        __syncwarp();
    };

    // Initial window: warp query z-span padded by PAD buckets.
    int bq_lo = min(NB - 1, max(0, (int)((zqmin - zminR) * invwR)));
    int bq_hi = min(NB - 1, max(0, (int)((zqmax - zminR) * invwR)));
    int blo = max(bq_lo - PAD, 0);
    int bhi = min(bq_hi + 1 + PAD, NB);
    scan(off[blo], off[bhi]);

    // Expansion with per-query union bounds (warp-uniform).
    for (;;) {
        float r0 = sqrtf(fmaxf(me[0] + qsq[0], 0.0f));
        float r1 = sqrtf(fmaxf(me[1] + qsq[1], 0.0f));
        float hi_need = wmax(fmaxf(zq[0] + r0, zq[1] + r1));
        float lo_need = wmin(fminf(zq[0] - r0, zq[1] - r1));

        bool okLo = (blo > 0)  && (zminR + (float)blo * wR > lo_need);
        bool okHi = (bhi < NB) && (zminR + (float)bhi * wR < hi_need);
        if (!okLo && !okHi) break;
        if (okLo) {
            int nlo = max(blo - BSTEP, 0);
            scan(off[nlo], off[blo]);
            blo = nlo;
        }
        if (okHi) {
            int nhi = min(bhi + BSTEP, NB);
            scan(off[bhi], off[nhi]);
            bhi = nhi;
        }
    }

    float* __restrict__ o = out + ((dir == 0) ? 0 : (size_t)B * Npts)
                          + (size_t)b * Npts;
    #pragma unroll
    for (int p = 0; p < QP; p++) {
        float d = fmaxf(me[p] + qsq[p], 0.0f);
        o[QI[qidx[p]]] = d;
    }
}

extern "C" void kernel_launch(void* const* d_in, const int* in_sizes, int n_in,
                              void* d_out, int out_size)
{
    const float* xyz1 = (const float*)d_in[0];
    const float* xyz2 = (const float*)d_in[1];
    float* out = (float*)d_out;

    const int B = 8;
    const int N = (in_sizes[0] / 3) / B;   // 8192 (== M)

    {
        dim3 grid(B, 2);
        cd_bucket_kernel<<<grid, ST>>>(xyz1, xyz2, N);
    }
    {
        int qblocks = N / (QT * QP);              // 32 CTAs per (b,dir)
        dim3 grid(qblocks, B, 2);                 // 512 CTAs
        cd_nn_kernel<<<grid, QT>>>(out, N, B);
    }
}